// round 1
// baseline (speedup 1.0000x reference)
#include <cuda_runtime.h>
#include <cstdint>

// Problem constants
#define L_SEQ  50
#define BATCH  256
#define DIN    256
#define LAT    512
#define HODE   1024
#define HID    1024          // 2*LAT
#define DSTRIDE 257          // data row stride (256 feats + dt)
#define OUT2_OFF (L_SEQ*BATCH*LAT)   // offset of new_h in d_out

// Scratch state (static device arrays: no allocation)
__device__ float g_S0[BATCH*LAT];
__device__ float g_S1[BATCH*LAT];
__device__ float g_Y [BATCH*LAT];
__device__ float g_Z [BATCH*HODE];

// ---------- packed f32x2 helpers (Blackwell fp32 2x FMA path) ----------
__device__ __forceinline__ unsigned long long pack2(float a, float b){
    unsigned long long r; asm("mov.b64 %0, {%1,%2};" : "=l"(r) : "f"(a), "f"(b)); return r;
}
__device__ __forceinline__ void unpack2(unsigned long long v, float& a, float& b){
    asm("mov.b64 {%0,%1}, %2;" : "=f"(a), "=f"(b) : "l"(v));
}
__device__ __forceinline__ unsigned long long fma2(unsigned long long a, unsigned long long b, unsigned long long c){
    unsigned long long d; asm("fma.rn.f32x2 %0, %1, %2, %3;" : "=l"(d) : "l"(a), "l"(b), "l"(c)); return d;
}

__device__ __forceinline__ float fsigmoid(float x){ return 1.0f/(1.0f + __expf(-x)); }
__device__ __forceinline__ float ftanh(float x){ return 1.0f - 2.0f/(__expf(2.0f*x) + 1.0f); }

// ---------- zero the initial state ----------
__global__ void k_zero(){
    int i = blockIdx.x*blockDim.x + threadIdx.x;
    if (i < BATCH*LAT) g_S0[i] = 0.0f;
}

// ---------- kernel 1: Z = tanh(Yin @ W1 + b1)   (256x512 @ 512x1024) ----------
// BM=32, BN=64, BK=32, 128 threads, per-thread 2 rows x 8 cols (4 f32x2 pairs)
__global__ __launch_bounds__(128) void k_mlp1(const float* __restrict__ Yin,
                                              const float* __restrict__ W1,
                                              const float* __restrict__ b1)
{
    __shared__ __align__(16) float As[32][33];
    __shared__ __align__(16) float Bs[32][64];
    const int tid = threadIdx.x;
    const int tx  = tid & 7;       // col group (8 cols each)
    const int ty  = tid >> 3;      // row group (2 rows each)
    const int m0  = blockIdx.y * 32;
    const int n0  = blockIdx.x * 64;

    unsigned long long acc[2][4];
    #pragma unroll
    for (int r = 0; r < 2; r++)
        #pragma unroll
        for (int j = 0; j < 4; j++) acc[r][j] = pack2(0.f, 0.f);

    for (int k0 = 0; k0 < LAT; k0 += 32) {
        #pragma unroll
        for (int q = 0; q < 2; q++) {               // A tile 32x32
            int idx = tid*2 + q;
            int ar = idx >> 3, ac4 = (idx & 7) * 4;
            float4 v = *(const float4*)&Yin[(m0+ar)*LAT + k0 + ac4];
            As[ar][ac4+0]=v.x; As[ar][ac4+1]=v.y; As[ar][ac4+2]=v.z; As[ar][ac4+3]=v.w;
        }
        #pragma unroll
        for (int q = 0; q < 4; q++) {               // B tile 32x64
            int idx = tid*4 + q;
            int br = idx >> 4, bc4 = (idx & 15) * 4;
            *(float4*)&Bs[br][bc4] = *(const float4*)&W1[(k0+br)*HODE + n0 + bc4];
        }
        __syncthreads();
        #pragma unroll
        for (int k = 0; k < 32; k++) {
            float a0 = As[ty*2+0][k];
            float a1 = As[ty*2+1][k];
            unsigned long long a0p = pack2(a0, a0);
            unsigned long long a1p = pack2(a1, a1);
            #pragma unroll
            for (int j = 0; j < 4; j++) {
                unsigned long long b = *(const unsigned long long*)&Bs[k][tx*8 + 2*j];
                acc[0][j] = fma2(a0p, b, acc[0][j]);
                acc[1][j] = fma2(a1p, b, acc[1][j]);
            }
        }
        __syncthreads();
    }
    #pragma unroll
    for (int r = 0; r < 2; r++) {
        int m = m0 + ty*2 + r;
        #pragma unroll
        for (int j = 0; j < 4; j++) {
            int n = n0 + tx*8 + 2*j;
            float x0, x1; unpack2(acc[r][j], x0, x1);
            g_Z[m*HODE + n    ] = ftanh(x0 + b1[n]);
            g_Z[m*HODE + n + 1] = ftanh(x1 + b1[n+1]);
        }
    }
}

// ---------- kernel 2: Yout = base + (Z @ W2 + b2) * (dt/3)  (256x1024 @ 1024x512) ----------
// BM=32, BN=32, BK=32, 128 threads, per-thread 2 rows x 4 cols (2 pairs)
__global__ __launch_bounds__(128) void k_mlp2(const float* __restrict__ base,
                                              const float* __restrict__ W2,
                                              const float* __restrict__ b2,
                                              const float* __restrict__ data,
                                              int t,
                                              float* __restrict__ Yout)
{
    __shared__ __align__(16) float As[32][33];
    __shared__ __align__(16) float Bs[32][32];
    const int tid = threadIdx.x;
    const int tx  = tid & 7;       // col group (4 cols each)
    const int ty  = tid >> 3;      // row group (2 rows each)
    const int m0  = blockIdx.y * 32;
    const int n0  = blockIdx.x * 32;

    unsigned long long acc[2][2];
    #pragma unroll
    for (int r = 0; r < 2; r++) { acc[r][0] = pack2(0.f,0.f); acc[r][1] = pack2(0.f,0.f); }

    for (int k0 = 0; k0 < HODE; k0 += 32) {
        #pragma unroll
        for (int q = 0; q < 2; q++) {               // A tile 32x32 from Z
            int idx = tid*2 + q;
            int ar = idx >> 3, ac4 = (idx & 7) * 4;
            float4 v = *(const float4*)&g_Z[(m0+ar)*HODE + k0 + ac4];
            As[ar][ac4+0]=v.x; As[ar][ac4+1]=v.y; As[ar][ac4+2]=v.z; As[ar][ac4+3]=v.w;
        }
        #pragma unroll
        for (int q = 0; q < 2; q++) {               // B tile 32x32
            int idx = tid*2 + q;
            int br = idx >> 3, bc4 = (idx & 7) * 4;
            *(float4*)&Bs[br][bc4] = *(const float4*)&W2[(k0+br)*LAT + n0 + bc4];
        }
        __syncthreads();
        #pragma unroll
        for (int k = 0; k < 32; k++) {
            float a0 = As[ty*2+0][k];
            float a1 = As[ty*2+1][k];
            unsigned long long a0p = pack2(a0, a0);
            unsigned long long a1p = pack2(a1, a1);
            #pragma unroll
            for (int j = 0; j < 2; j++) {
                unsigned long long b = *(const unsigned long long*)&Bs[k][tx*4 + 2*j];
                acc[0][j] = fma2(a0p, b, acc[0][j]);
                acc[1][j] = fma2(a1p, b, acc[1][j]);
            }
        }
        __syncthreads();
    }
    #pragma unroll
    for (int r = 0; r < 2; r++) {
        int m = m0 + ty*2 + r;
        float hstep = data[(size_t)(t*BATCH + m)*DSTRIDE + DIN] * (1.0f/3.0f);
        #pragma unroll
        for (int j = 0; j < 2; j++) {
            int n = n0 + tx*4 + 2*j;
            float x0, x1; unpack2(acc[r][j], x0, x1);
            Yout[m*LAT + n    ] = base[m*LAT + n    ] + (x0 + b2[n  ]) * hstep;
            Yout[m*LAT + n + 1] = base[m*LAT + n + 1] + (x1 + b2[n+1]) * hstep;
        }
    }
}

// ---------- kernel 3: fused GRU cell (gi GEMM + gh GEMM + gates) ----------
// out cols j in [0, J): J=512 normally (only new_h[:, :512] is ever used),
// J=1024 on the last step (full new_h is an output).
// gates at j use W rows {j, 1024+j, 2048+j}. h = [Y | S].
__global__ __launch_bounds__(128) void k_gru(const float* __restrict__ data, int t,
                                             const float* __restrict__ Wih,
                                             const float* __restrict__ bih,
                                             const float* __restrict__ Whh,
                                             const float* __restrict__ bhh,
                                             const float* __restrict__ Sread,
                                             float* __restrict__ Swrite,
                                             float* __restrict__ out)
{
    __shared__ __align__(16) float Hs[32][33];   // h / x tile (rows=samples)
    __shared__ __align__(16) float Wr[32][34];   // [k][j], transposed weights
    __shared__ __align__(16) float Wz[32][34];
    __shared__ __align__(16) float Wn[32][34];

    const int tid = threadIdx.x;
    const int tx  = tid & 7;       // col group (4 cols each)
    const int ty  = tid >> 3;      // row group (2 rows each)
    const int i0  = blockIdx.y * 32;   // sample tile
    const int j0  = blockIdx.x * 32;   // gate-col tile

    unsigned long long ar_[2][2], az_[2][2], aghn[2][2], agin[2][2];
    #pragma unroll
    for (int r = 0; r < 2; r++)
        #pragma unroll
        for (int j = 0; j < 2; j++) {
            ar_[r][j]=pack2(0.f,0.f); az_[r][j]=pack2(0.f,0.f);
            aghn[r][j]=pack2(0.f,0.f); agin[r][j]=pack2(0.f,0.f);
        }

    // ---- gh part: K=1024 over h = [Y | S] ----
    for (int k0 = 0; k0 < HID; k0 += 32) {
        const float* src = (k0 < LAT) ? g_Y : Sread;
        const int kc = (k0 < LAT) ? k0 : (k0 - LAT);
        #pragma unroll
        for (int q = 0; q < 2; q++) {               // h tile 32x32
            int idx = tid*2 + q;
            int hr = idx >> 3, hc4 = (idx & 7) * 4;
            float4 v = *(const float4*)&src[(i0+hr)*LAT + kc + hc4];
            Hs[hr][hc4+0]=v.x; Hs[hr][hc4+1]=v.y; Hs[hr][hc4+2]=v.z; Hs[hr][hc4+3]=v.w;
        }
        #pragma unroll
        for (int g = 0; g < 3; g++) {               // 3 gate weight tiles (transposed)
            #pragma unroll
            for (int q = 0; q < 2; q++) {
                int idx = tid*2 + q;
                int wj = idx >> 3, wk4 = (idx & 7) * 4;
                float4 v = *(const float4*)&Whh[(size_t)(g*HID + j0 + wj)*HID + k0 + wk4];
                float* W = (g==0) ? &Wr[0][0] : (g==1) ? &Wz[0][0] : &Wn[0][0];
                W[(wk4+0)*34 + wj]=v.x; W[(wk4+1)*34 + wj]=v.y;
                W[(wk4+2)*34 + wj]=v.z; W[(wk4+3)*34 + wj]=v.w;
            }
        }
        __syncthreads();
        #pragma unroll
        for (int k = 0; k < 32; k++) {
            float h0 = Hs[ty*2+0][k];
            float h1 = Hs[ty*2+1][k];
            unsigned long long a0p = pack2(h0,h0);
            unsigned long long a1p = pack2(h1,h1);
            #pragma unroll
            for (int j = 0; j < 2; j++) {
                unsigned long long br = *(const unsigned long long*)&Wr[k][tx*4 + 2*j];
                unsigned long long bz = *(const unsigned long long*)&Wz[k][tx*4 + 2*j];
                unsigned long long bn = *(const unsigned long long*)&Wn[k][tx*4 + 2*j];
                ar_[0][j] = fma2(a0p, br, ar_[0][j]);  ar_[1][j] = fma2(a1p, br, ar_[1][j]);
                az_[0][j] = fma2(a0p, bz, az_[0][j]);  az_[1][j] = fma2(a1p, bz, az_[1][j]);
                aghn[0][j] = fma2(a0p, bn, aghn[0][j]); aghn[1][j] = fma2(a1p, bn, aghn[1][j]);
            }
        }
        __syncthreads();
    }

    // ---- gi part: K=256 over x = data[t, :, :256] ----
    for (int k0 = 0; k0 < DIN; k0 += 32) {
        #pragma unroll
        for (int q = 0; q < 8; q++) {               // x tile 32x32 (scalar: rows stride 257)
            int idx = tid + q*128;
            int xi = idx >> 5, xk = idx & 31;
            Hs[xi][xk] = data[(size_t)(t*BATCH + i0 + xi)*DSTRIDE + k0 + xk];
        }
        #pragma unroll
        for (int g = 0; g < 3; g++) {
            #pragma unroll
            for (int q = 0; q < 2; q++) {
                int idx = tid*2 + q;
                int wj = idx >> 3, wk4 = (idx & 7) * 4;
                float4 v = *(const float4*)&Wih[(size_t)(g*HID + j0 + wj)*DIN + k0 + wk4];
                float* W = (g==0) ? &Wr[0][0] : (g==1) ? &Wz[0][0] : &Wn[0][0];
                W[(wk4+0)*34 + wj]=v.x; W[(wk4+1)*34 + wj]=v.y;
                W[(wk4+2)*34 + wj]=v.z; W[(wk4+3)*34 + wj]=v.w;
            }
        }
        __syncthreads();
        #pragma unroll
        for (int k = 0; k < 32; k++) {
            float x0 = Hs[ty*2+0][k];
            float x1 = Hs[ty*2+1][k];
            unsigned long long a0p = pack2(x0,x0);
            unsigned long long a1p = pack2(x1,x1);
            #pragma unroll
            for (int j = 0; j < 2; j++) {
                unsigned long long br = *(const unsigned long long*)&Wr[k][tx*4 + 2*j];
                unsigned long long bz = *(const unsigned long long*)&Wz[k][tx*4 + 2*j];
                unsigned long long bn = *(const unsigned long long*)&Wn[k][tx*4 + 2*j];
                ar_[0][j] = fma2(a0p, br, ar_[0][j]);  ar_[1][j] = fma2(a1p, br, ar_[1][j]);
                az_[0][j] = fma2(a0p, bz, az_[0][j]);  az_[1][j] = fma2(a1p, bz, az_[1][j]);
                agin[0][j] = fma2(a0p, bn, agin[0][j]); agin[1][j] = fma2(a1p, bn, agin[1][j]);
            }
        }
        __syncthreads();
    }

    // ---- gates + write ----
    const bool last = (t == L_SEQ - 1);
    #pragma unroll
    for (int r = 0; r < 2; r++) {
        int i = i0 + ty*2 + r;
        #pragma unroll
        for (int j = 0; j < 2; j++) {
            int nb = j0 + tx*4 + 2*j;
            float r0,r1, z0,z1, gn0,gn1, in0,in1;
            unpack2(ar_[r][j], r0, r1);
            unpack2(az_[r][j], z0, z1);
            unpack2(aghn[r][j], gn0, gn1);
            unpack2(agin[r][j], in0, in1);
            #pragma unroll
            for (int h = 0; h < 2; h++) {
                int jj = nb + h;
                float sr  = (h==0)? r0 : r1;
                float sz  = (h==0)? z0 : z1;
                float ghn = (h==0)? gn0: gn1;
                float gin = (h==0)? in0: in1;
                float rg = fsigmoid(sr + bih[jj] + bhh[jj]);
                float zg = fsigmoid(sz + bih[HID+jj] + bhh[HID+jj]);
                float ng = ftanh((gin + bih[2*HID+jj]) + rg * (ghn + bhh[2*HID+jj]));
                float hj = (jj < LAT) ? g_Y[i*LAT + jj] : Sread[i*LAT + jj - LAT];
                float v = (1.0f - zg) * ng + zg * hj;
                if (jj < LAT) {
                    out[(size_t)(t*BATCH + i)*LAT + jj] = v;
                    Swrite[i*LAT + jj] = v;
                }
                if (last) out[OUT2_OFF + (size_t)i*HID + jj] = v;
            }
        }
    }
}

extern "C" void kernel_launch(void* const* d_in, const int* in_sizes, int n_in,
                              void* d_out, int out_size)
{
    const float* data = (const float*)d_in[0];
    const float* w1   = (const float*)d_in[1];
    const float* b1   = (const float*)d_in[2];
    const float* w2   = (const float*)d_in[3];
    const float* b2   = (const float*)d_in[4];
    const float* wih  = (const float*)d_in[5];
    const float* bih  = (const float*)d_in[6];
    const float* whh  = (const float*)d_in[7];
    const float* bhh  = (const float*)d_in[8];
    float* out = (float*)d_out;

    float *S0, *S1, *Y;
    cudaGetSymbolAddress((void**)&S0, g_S0);
    cudaGetSymbolAddress((void**)&S1, g_S1);
    cudaGetSymbolAddress((void**)&Y,  g_Y);

    k_zero<<<(BATCH*LAT + 255)/256, 256>>>();

    dim3 g1(HODE/64, BATCH/32);   // (16, 8) for mlp1
    dim3 g2(LAT/32,  BATCH/32);   // (16, 8) for mlp2

    for (int t = 0; t < L_SEQ; t++) {
        float* Sr = (t & 1) ? S1 : S0;
        float* Sw = (t & 1) ? S0 : S1;

        // 3 Euler substeps: y0 = s;  y <- y + f(y)*dt/3
        k_mlp1<<<g1, 128>>>(Sr, w1, b1);
        k_mlp2<<<g2, 128>>>(Sr, w2, b2, data, t, Y);
        k_mlp1<<<g1, 128>>>(Y,  w1, b1);
        k_mlp2<<<g2, 128>>>(Y,  w2, b2, data, t, Y);
        k_mlp1<<<g1, 128>>>(Y,  w1, b1);
        k_mlp2<<<g2, 128>>>(Y,  w2, b2, data, t, Y);

        // GRU: only first 512 columns needed except on the last step
        int J = (t == L_SEQ - 1) ? HID : LAT;
        dim3 g3(J/32, BATCH/32);
        k_gru<<<g3, 128>>>(data, t, wih, bih, whh, bhh, Sr, Sw, out);
    }
    (void)in_sizes; (void)n_in; (void)out_size;
}

// round 2
// speedup vs baseline: 1.0466x; 1.0466x over previous
#include <cuda_runtime.h>
#include <cstdint>

// Problem constants
#define L_SEQ  50
#define BATCH  256
#define DIN    256
#define LAT    512
#define HODE   1024
#define HID    1024          // 2*LAT
#define DSTRIDE 257          // data row stride (256 feats + dt)
#define OUT2_OFF (L_SEQ*BATCH*LAT)   // offset of new_h in d_out

// Scratch state (static device arrays: no allocation)
__device__ float g_S0[BATCH*LAT];
__device__ float g_S1[BATCH*LAT];
__device__ float g_Y [BATCH*LAT];
__device__ float g_Z [BATCH*HODE];

// ---------- packed f32x2 helpers (Blackwell fp32 2x FMA path) ----------
__device__ __forceinline__ unsigned long long pack2(float a, float b){
    unsigned long long r; asm("mov.b64 %0, {%1,%2};" : "=l"(r) : "f"(a), "f"(b)); return r;
}
__device__ __forceinline__ void unpack2(unsigned long long v, float& a, float& b){
    asm("mov.b64 {%0,%1}, %2;" : "=f"(a), "=f"(b) : "l"(v));
}
__device__ __forceinline__ unsigned long long fma2(unsigned long long a, unsigned long long b, unsigned long long c){
    unsigned long long d; asm("fma.rn.f32x2 %0, %1, %2, %3;" : "=l"(d) : "l"(a), "l"(b), "l"(c)); return d;
}

__device__ __forceinline__ float fsigmoid(float x){ return 1.0f/(1.0f + __expf(-x)); }
__device__ __forceinline__ float ftanh(float x){ return 1.0f - 2.0f/(__expf(2.0f*x) + 1.0f); }

// ---------- zero the initial state ----------
__global__ void k_zero(){
    int i = blockIdx.x*blockDim.x + threadIdx.x;
    if (i < BATCH*LAT) g_S0[i] = 0.0f;
}

// ---------- kernel 1: Z = tanh(Yin @ W1 + b1)   (256x512 @ 512x1024) ----------
// BM=32, BN=64, BK=32, 128 threads, per-thread 2 rows x 8 cols (4 f32x2 pairs)
__global__ __launch_bounds__(128) void k_mlp1(const float* __restrict__ Yin,
                                              const float* __restrict__ W1,
                                              const float* __restrict__ b1)
{
    __shared__ __align__(16) float As[32][33];
    __shared__ __align__(16) float Bs[32][64];
    const int tid = threadIdx.x;
    const int tx  = tid & 7;       // col group (8 cols each)
    const int ty  = tid >> 3;      // row group (2 rows each)
    const int m0  = blockIdx.y * 32;
    const int n0  = blockIdx.x * 64;

    unsigned long long acc[2][4];
    #pragma unroll
    for (int r = 0; r < 2; r++)
        #pragma unroll
        for (int j = 0; j < 4; j++) acc[r][j] = pack2(0.f, 0.f);

    for (int k0 = 0; k0 < LAT; k0 += 32) {
        #pragma unroll
        for (int q = 0; q < 2; q++) {               // A tile 32x32
            int idx = tid*2 + q;
            int ar = idx >> 3, ac4 = (idx & 7) * 4;
            float4 v = *(const float4*)&Yin[(m0+ar)*LAT + k0 + ac4];
            As[ar][ac4+0]=v.x; As[ar][ac4+1]=v.y; As[ar][ac4+2]=v.z; As[ar][ac4+3]=v.w;
        }
        #pragma unroll
        for (int q = 0; q < 4; q++) {               // B tile 32x64
            int idx = tid*4 + q;
            int br = idx >> 4, bc4 = (idx & 15) * 4;
            *(float4*)&Bs[br][bc4] = *(const float4*)&W1[(k0+br)*HODE + n0 + bc4];
        }
        __syncthreads();
        #pragma unroll
        for (int k = 0; k < 32; k++) {
            float a0 = As[ty*2+0][k];
            float a1 = As[ty*2+1][k];
            unsigned long long a0p = pack2(a0, a0);
            unsigned long long a1p = pack2(a1, a1);
            #pragma unroll
            for (int j = 0; j < 4; j++) {
                unsigned long long b = *(const unsigned long long*)&Bs[k][tx*8 + 2*j];
                acc[0][j] = fma2(a0p, b, acc[0][j]);
                acc[1][j] = fma2(a1p, b, acc[1][j]);
            }
        }
        __syncthreads();
    }
    #pragma unroll
    for (int r = 0; r < 2; r++) {
        int m = m0 + ty*2 + r;
        #pragma unroll
        for (int j = 0; j < 4; j++) {
            int n = n0 + tx*8 + 2*j;
            float x0, x1; unpack2(acc[r][j], x0, x1);
            g_Z[m*HODE + n    ] = ftanh(x0 + b1[n]);
            g_Z[m*HODE + n + 1] = ftanh(x1 + b1[n+1]);
        }
    }
}

// ---------- kernel 2: Yout = base + (Z @ W2 + b2) * (dt/3)  (256x1024 @ 1024x512) ----------
// BM=32, BN=32, BK=32, 128 threads, per-thread 2 rows x 4 cols (2 pairs)
__global__ __launch_bounds__(128) void k_mlp2(const float* __restrict__ base,
                                              const float* __restrict__ W2,
                                              const float* __restrict__ b2,
                                              const float* __restrict__ data,
                                              int t,
                                              float* __restrict__ Yout)
{
    __shared__ __align__(16) float As[32][33];
    __shared__ __align__(16) float Bs[32][32];
    const int tid = threadIdx.x;
    const int tx  = tid & 7;       // col group (4 cols each)
    const int ty  = tid >> 3;      // row group (2 rows each)
    const int m0  = blockIdx.y * 32;
    const int n0  = blockIdx.x * 32;

    unsigned long long acc[2][2];
    #pragma unroll
    for (int r = 0; r < 2; r++) { acc[r][0] = pack2(0.f,0.f); acc[r][1] = pack2(0.f,0.f); }

    for (int k0 = 0; k0 < HODE; k0 += 32) {
        #pragma unroll
        for (int q = 0; q < 2; q++) {               // A tile 32x32 from Z
            int idx = tid*2 + q;
            int ar = idx >> 3, ac4 = (idx & 7) * 4;
            float4 v = *(const float4*)&g_Z[(m0+ar)*HODE + k0 + ac4];
            As[ar][ac4+0]=v.x; As[ar][ac4+1]=v.y; As[ar][ac4+2]=v.z; As[ar][ac4+3]=v.w;
        }
        #pragma unroll
        for (int q = 0; q < 2; q++) {               // B tile 32x32
            int idx = tid*2 + q;
            int br = idx >> 3, bc4 = (idx & 7) * 4;
            *(float4*)&Bs[br][bc4] = *(const float4*)&W2[(k0+br)*LAT + n0 + bc4];
        }
        __syncthreads();
        #pragma unroll
        for (int k = 0; k < 32; k++) {
            float a0 = As[ty*2+0][k];
            float a1 = As[ty*2+1][k];
            unsigned long long a0p = pack2(a0, a0);
            unsigned long long a1p = pack2(a1, a1);
            #pragma unroll
            for (int j = 0; j < 2; j++) {
                unsigned long long b = *(const unsigned long long*)&Bs[k][tx*4 + 2*j];
                acc[0][j] = fma2(a0p, b, acc[0][j]);
                acc[1][j] = fma2(a1p, b, acc[1][j]);
            }
        }
        __syncthreads();
    }
    #pragma unroll
    for (int r = 0; r < 2; r++) {
        int m = m0 + ty*2 + r;
        float hstep = data[(size_t)(t*BATCH + m)*DSTRIDE + DIN] * (1.0f/3.0f);
        #pragma unroll
        for (int j = 0; j < 2; j++) {
            int n = n0 + tx*4 + 2*j;
            float x0, x1; unpack2(acc[r][j], x0, x1);
            Yout[m*LAT + n    ] = base[m*LAT + n    ] + (x0 + b2[n  ]) * hstep;
            Yout[m*LAT + n + 1] = base[m*LAT + n + 1] + (x1 + b2[n+1]) * hstep;
        }
    }
}

// ---------- kernel 3: fused GRU cell (gi GEMM + gh GEMM + gates) ----------
// out cols j in [0, J): J=512 normally (only new_h[:, :512] is ever used),
// J=1024 on the last step (full new_h is an output).
// gates at j use W rows {j, 1024+j, 2048+j}. h = [Y | S].
__global__ __launch_bounds__(128) void k_gru(const float* __restrict__ data, int t,
                                             const float* __restrict__ Wih,
                                             const float* __restrict__ bih,
                                             const float* __restrict__ Whh,
                                             const float* __restrict__ bhh,
                                             const float* __restrict__ Sread,
                                             float* __restrict__ Swrite,
                                             float* __restrict__ out)
{
    __shared__ __align__(16) float Hs[32][33];   // h / x tile (rows=samples)
    __shared__ __align__(16) float Wr[32][34];   // [k][j], transposed weights
    __shared__ __align__(16) float Wz[32][34];
    __shared__ __align__(16) float Wn[32][34];

    const int tid = threadIdx.x;
    const int tx  = tid & 7;       // col group (4 cols each)
    const int ty  = tid >> 3;      // row group (2 rows each)
    const int i0  = blockIdx.y * 32;   // sample tile
    const int j0  = blockIdx.x * 32;   // gate-col tile

    unsigned long long ar_[2][2], az_[2][2], aghn[2][2], agin[2][2];
    #pragma unroll
    for (int r = 0; r < 2; r++)
        #pragma unroll
        for (int j = 0; j < 2; j++) {
            ar_[r][j]=pack2(0.f,0.f); az_[r][j]=pack2(0.f,0.f);
            aghn[r][j]=pack2(0.f,0.f); agin[r][j]=pack2(0.f,0.f);
        }

    // ---- gh part: K=1024 over h = [Y | S] ----
    for (int k0 = 0; k0 < HID; k0 += 32) {
        const float* src = (k0 < LAT) ? g_Y : Sread;
        const int kc = (k0 < LAT) ? k0 : (k0 - LAT);
        #pragma unroll
        for (int q = 0; q < 2; q++) {               // h tile 32x32
            int idx = tid*2 + q;
            int hr = idx >> 3, hc4 = (idx & 7) * 4;
            float4 v = *(const float4*)&src[(i0+hr)*LAT + kc + hc4];
            Hs[hr][hc4+0]=v.x; Hs[hr][hc4+1]=v.y; Hs[hr][hc4+2]=v.z; Hs[hr][hc4+3]=v.w;
        }
        #pragma unroll
        for (int g = 0; g < 3; g++) {               // 3 gate weight tiles (transposed)
            #pragma unroll
            for (int q = 0; q < 2; q++) {
                int idx = tid*2 + q;
                int wj = idx >> 3, wk4 = (idx & 7) * 4;
                float4 v = *(const float4*)&Whh[(size_t)(g*HID + j0 + wj)*HID + k0 + wk4];
                float* W = (g==0) ? &Wr[0][0] : (g==1) ? &Wz[0][0] : &Wn[0][0];
                W[(wk4+0)*34 + wj]=v.x; W[(wk4+1)*34 + wj]=v.y;
                W[(wk4+2)*34 + wj]=v.z; W[(wk4+3)*34 + wj]=v.w;
            }
        }
        __syncthreads();
        #pragma unroll
        for (int k = 0; k < 32; k++) {
            float h0 = Hs[ty*2+0][k];
            float h1 = Hs[ty*2+1][k];
            unsigned long long a0p = pack2(h0,h0);
            unsigned long long a1p = pack2(h1,h1);
            #pragma unroll
            for (int j = 0; j < 2; j++) {
                unsigned long long br = *(const unsigned long long*)&Wr[k][tx*4 + 2*j];
                unsigned long long bz = *(const unsigned long long*)&Wz[k][tx*4 + 2*j];
                unsigned long long bn = *(const unsigned long long*)&Wn[k][tx*4 + 2*j];
                ar_[0][j] = fma2(a0p, br, ar_[0][j]);  ar_[1][j] = fma2(a1p, br, ar_[1][j]);
                az_[0][j] = fma2(a0p, bz, az_[0][j]);  az_[1][j] = fma2(a1p, bz, az_[1][j]);
                aghn[0][j] = fma2(a0p, bn, aghn[0][j]); aghn[1][j] = fma2(a1p, bn, aghn[1][j]);
            }
        }
        __syncthreads();
    }

    // ---- gi part: K=256 over x = data[t, :, :256] ----
    for (int k0 = 0; k0 < DIN; k0 += 32) {
        #pragma unroll
        for (int q = 0; q < 8; q++) {               // x tile 32x32 (scalar: rows stride 257)
            int idx = tid + q*128;
            int xi = idx >> 5, xk = idx & 31;
            Hs[xi][xk] = data[(size_t)(t*BATCH + i0 + xi)*DSTRIDE + k0 + xk];
        }
        #pragma unroll
        for (int g = 0; g < 3; g++) {
            #pragma unroll
            for (int q = 0; q < 2; q++) {
                int idx = tid*2 + q;
                int wj = idx >> 3, wk4 = (idx & 7) * 4;
                float4 v = *(const float4*)&Wih[(size_t)(g*HID + j0 + wj)*DIN + k0 + wk4];
                float* W = (g==0) ? &Wr[0][0] : (g==1) ? &Wz[0][0] : &Wn[0][0];
                W[(wk4+0)*34 + wj]=v.x; W[(wk4+1)*34 + wj]=v.y;
                W[(wk4+2)*34 + wj]=v.z; W[(wk4+3)*34 + wj]=v.w;
            }
        }
        __syncthreads();
        #pragma unroll
        for (int k = 0; k < 32; k++) {
            float x0 = Hs[ty*2+0][k];
            float x1 = Hs[ty*2+1][k];
            unsigned long long a0p = pack2(x0,x0);
            unsigned long long a1p = pack2(x1,x1);
            #pragma unroll
            for (int j = 0; j < 2; j++) {
                unsigned long long br = *(const unsigned long long*)&Wr[k][tx*4 + 2*j];
                unsigned long long bz = *(const unsigned long long*)&Wz[k][tx*4 + 2*j];
                unsigned long long bn = *(const unsigned long long*)&Wn[k][tx*4 + 2*j];
                ar_[0][j] = fma2(a0p, br, ar_[0][j]);  ar_[1][j] = fma2(a1p, br, ar_[1][j]);
                az_[0][j] = fma2(a0p, bz, az_[0][j]);  az_[1][j] = fma2(a1p, bz, az_[1][j]);
                agin[0][j] = fma2(a0p, bn, agin[0][j]); agin[1][j] = fma2(a1p, bn, agin[1][j]);
            }
        }
        __syncthreads();
    }

    // ---- gates + write ----
    const bool last = (t == L_SEQ - 1);
    #pragma unroll
    for (int r = 0; r < 2; r++) {
        int i = i0 + ty*2 + r;
        #pragma unroll
        for (int j = 0; j < 2; j++) {
            int nb = j0 + tx*4 + 2*j;
            float r0,r1, z0,z1, gn0,gn1, in0,in1;
            unpack2(ar_[r][j], r0, r1);
            unpack2(az_[r][j], z0, z1);
            unpack2(aghn[r][j], gn0, gn1);
            unpack2(agin[r][j], in0, in1);
            #pragma unroll
            for (int h = 0; h < 2; h++) {
                int jj = nb + h;
                float sr  = (h==0)? r0 : r1;
                float sz  = (h==0)? z0 : z1;
                float ghn = (h==0)? gn0: gn1;
                float gin = (h==0)? in0: in1;
                float rg = fsigmoid(sr + bih[jj] + bhh[jj]);
                float zg = fsigmoid(sz + bih[HID+jj] + bhh[HID+jj]);
                float ng = ftanh((gin + bih[2*HID+jj]) + rg * (ghn + bhh[2*HID+jj]));
                float hj = (jj < LAT) ? g_Y[i*LAT + jj] : Sread[i*LAT + jj - LAT];
                float v = (1.0f - zg) * ng + zg * hj;
                if (jj < LAT) {
                    out[(size_t)(t*BATCH + i)*LAT + jj] = v;
                    Swrite[i*LAT + jj] = v;
                }
                if (last) out[OUT2_OFF + (size_t)i*HID + jj] = v;
            }
        }
    }
}

extern "C" void kernel_launch(void* const* d_in, const int* in_sizes, int n_in,
                              void* d_out, int out_size)
{
    const float* data = (const float*)d_in[0];
    const float* w1   = (const float*)d_in[1];
    const float* b1   = (const float*)d_in[2];
    const float* w2   = (const float*)d_in[3];
    const float* b2   = (const float*)d_in[4];
    const float* wih  = (const float*)d_in[5];
    const float* bih  = (const float*)d_in[6];
    const float* whh  = (const float*)d_in[7];
    const float* bhh  = (const float*)d_in[8];
    float* out = (float*)d_out;

    float *S0, *S1, *Y;
    cudaGetSymbolAddress((void**)&S0, g_S0);
    cudaGetSymbolAddress((void**)&S1, g_S1);
    cudaGetSymbolAddress((void**)&Y,  g_Y);

    k_zero<<<(BATCH*LAT + 255)/256, 256>>>();

    dim3 g1(HODE/64, BATCH/32);   // (16, 8) for mlp1
    dim3 g2(LAT/32,  BATCH/32);   // (16, 8) for mlp2

    for (int t = 0; t < L_SEQ; t++) {
        float* Sr = (t & 1) ? S1 : S0;
        float* Sw = (t & 1) ? S0 : S1;

        // 3 Euler substeps: y0 = s;  y <- y + f(y)*dt/3
        k_mlp1<<<g1, 128>>>(Sr, w1, b1);
        k_mlp2<<<g2, 128>>>(Sr, w2, b2, data, t, Y);
        k_mlp1<<<g1, 128>>>(Y,  w1, b1);
        k_mlp2<<<g2, 128>>>(Y,  w2, b2, data, t, Y);
        k_mlp1<<<g1, 128>>>(Y,  w1, b1);
        k_mlp2<<<g2, 128>>>(Y,  w2, b2, data, t, Y);

        // GRU: only first 512 columns needed except on the last step
        int J = (t == L_SEQ - 1) ? HID : LAT;
        dim3 g3(J/32, BATCH/32);
        k_gru<<<g3, 128>>>(data, t, wih, bih, whh, bhh, Sr, Sw, out);
    }
    (void)in_sizes; (void)n_in; (void)out_size;
}

// round 3
// speedup vs baseline: 1.1902x; 1.1372x over previous
#include <cuda_runtime.h>
#include <cstdint>

#define L_SEQ  50
#define BATCH  256
#define DIN    256
#define LAT    512
#define HODE   1024
#define HID    1024
#define DSTRIDE 257
#define JC     3072                     // transposed gate-weight row length
#define OUT2_OFF (L_SEQ*BATCH*LAT)

using u64 = unsigned long long;

__device__ float g_S0[BATCH*LAT];
__device__ float g_S1[BATCH*LAT];
__device__ float g_Y [BATCH*LAT];
__device__ float g_Z [BATCH*HODE];
__device__ float g_WihT[DIN*JC];        // [k][g*1024+j]
__device__ float g_WhhT[HID*JC];

__device__ __forceinline__ u64 pack2(float a, float b){
    u64 r; asm("mov.b64 %0, {%1,%2};" : "=l"(r) : "f"(a), "f"(b)); return r;
}
__device__ __forceinline__ void unpack2(u64 v, float& a, float& b){
    asm("mov.b64 {%0,%1}, %2;" : "=f"(a), "=f"(b) : "l"(v));
}
__device__ __forceinline__ u64 fma2(u64 a, u64 b, u64 c){
    u64 d; asm("fma.rn.f32x2 %0, %1, %2, %3;" : "=l"(d) : "l"(a), "l"(b), "l"(c)); return d;
}
__device__ __forceinline__ float fsigmoid(float x){ return 1.0f/(1.0f + __expf(-x)); }
__device__ __forceinline__ float ftanh(float x){ return 1.0f - 2.0f/(__expf(2.0f*x) + 1.0f); }

__global__ void k_zero(){
    int i = blockIdx.x*blockDim.x + threadIdx.x;
    if (i < BATCH*LAT) g_S0[i] = 0.0f;
}

// W[3072][K] row-major -> WT[K][3072]
__global__ __launch_bounds__(256) void k_transpose(const float* __restrict__ W, int K,
                                                   float* __restrict__ WT)
{
    __shared__ float tile[32][33];
    const int j0 = blockIdx.x*32, k0 = blockIdx.y*32;
    const int r = threadIdx.x >> 3, c4 = (threadIdx.x & 7)*4;
    float4 v = *(const float4*)&W[(size_t)(j0+r)*K + k0 + c4];
    tile[r][c4+0]=v.x; tile[r][c4+1]=v.y; tile[r][c4+2]=v.z; tile[r][c4+3]=v.w;
    __syncthreads();
    float4 o = make_float4(tile[c4+0][r], tile[c4+1][r], tile[c4+2][r], tile[c4+3][r]);
    *(float4*)&WT[(size_t)(k0+r)*JC + j0 + c4] = o;
}

// ---------------- mlp1: g_Z = tanh(Yin @ W1 + b1), 256x512 @ 512x1024 ----------------
// BM=32, BN=64, BK=32, 256 threads; per-thread 2 rows x 4 cols.
__global__ __launch_bounds__(256) void k_mlp1(const float* __restrict__ Yin,
                                              const float* __restrict__ W1,
                                              const float* __restrict__ b1)
{
    __shared__ __align__(16) u64   As[2][32][34];
    __shared__ __align__(16) float Bs[2][32][68];
    const int tid = threadIdx.x;
    const int tx = tid & 15, ty = tid >> 4;
    const int m0 = blockIdx.y*32, n0 = blockIdx.x*64;
    const int sm = tid >> 3, sk = (tid & 7)*4;         // A staging
    const int br = tid >> 3, bc = (tid & 7)*8;         // B staging

    float4 pa, pb0, pb1;
    u64 acc[2][2];
    acc[0][0]=pack2(0.f,0.f); acc[0][1]=acc[0][0]; acc[1][0]=acc[0][0]; acc[1][1]=acc[0][0];

    auto ldg = [&](int k0){
        pa = *(const float4*)&Yin[(size_t)(m0+sm)*LAT + k0 + sk];
        const float* p = &W1[(size_t)(k0+br)*HODE + n0 + bc];
        pb0 = *(const float4*)p; pb1 = *(const float4*)(p+4);
    };
    auto sts = [&](int b){
        As[b][sk+0][sm]=pack2(pa.x,pa.x); As[b][sk+1][sm]=pack2(pa.y,pa.y);
        As[b][sk+2][sm]=pack2(pa.z,pa.z); As[b][sk+3][sm]=pack2(pa.w,pa.w);
        *(float4*)&Bs[b][br][bc] = pb0;  *(float4*)&Bs[b][br][bc+4] = pb1;
    };

    ldg(0); sts(0); __syncthreads();
    for (int kt = 0; kt < 16; kt++){
        int c = kt & 1;
        if (kt < 15) ldg((kt+1)*32);
        #pragma unroll
        for (int k = 0; k < 32; k++){
            ulonglong2 a = *(const ulonglong2*)&As[c][k][ty*2];
            ulonglong2 b = *(const ulonglong2*)&Bs[c][k][tx*4];
            acc[0][0]=fma2(a.x,b.x,acc[0][0]); acc[0][1]=fma2(a.x,b.y,acc[0][1]);
            acc[1][0]=fma2(a.y,b.x,acc[1][0]); acc[1][1]=fma2(a.y,b.y,acc[1][1]);
        }
        if (kt < 15) sts(c^1);
        __syncthreads();
    }
    #pragma unroll
    for (int r = 0; r < 2; r++){
        int m = m0 + ty*2 + r;
        #pragma unroll
        for (int p = 0; p < 2; p++){
            float x0,x1; unpack2(acc[r][p], x0, x1);
            int n = n0 + tx*4 + p*2;
            g_Z[(size_t)m*HODE + n  ] = ftanh(x0 + b1[n]);
            g_Z[(size_t)m*HODE + n+1] = ftanh(x1 + b1[n+1]);
        }
    }
}

// ---------------- mlp2: Yout = base + (g_Z @ W2 + b2)*dt/3, 256x1024 @ 1024x512 ------
// BM=32, BN=32, BK=32, 256 threads; per-thread 2 rows x 2 cols.
__global__ __launch_bounds__(256) void k_mlp2(const float* __restrict__ base,
                                              const float* __restrict__ W2,
                                              const float* __restrict__ b2,
                                              const float* __restrict__ data, int t,
                                              float* __restrict__ Yout)
{
    __shared__ __align__(16) u64   As[2][32][34];
    __shared__ __align__(16) float Bs[2][32][36];
    const int tid = threadIdx.x;
    const int tx = tid & 15, ty = tid >> 4;
    const int m0 = blockIdx.y*32, n0 = blockIdx.x*32;
    const int sm = tid >> 3, sk = (tid & 7)*4;

    float4 pa, pb;
    u64 acc[2];
    acc[0]=pack2(0.f,0.f); acc[1]=acc[0];

    auto ldg = [&](int k0){
        pa = *(const float4*)&g_Z[(size_t)(m0+sm)*HODE + k0 + sk];
        pb = *(const float4*)&W2[(size_t)(k0+sm)*LAT + n0 + sk];
    };
    auto sts = [&](int b){
        As[b][sk+0][sm]=pack2(pa.x,pa.x); As[b][sk+1][sm]=pack2(pa.y,pa.y);
        As[b][sk+2][sm]=pack2(pa.z,pa.z); As[b][sk+3][sm]=pack2(pa.w,pa.w);
        *(float4*)&Bs[b][sm][sk] = pb;
    };

    ldg(0); sts(0); __syncthreads();
    for (int kt = 0; kt < 32; kt++){
        int c = kt & 1;
        if (kt < 31) ldg((kt+1)*32);
        #pragma unroll
        for (int k = 0; k < 32; k++){
            ulonglong2 a = *(const ulonglong2*)&As[c][k][ty*2];
            u64 b = *(const u64*)&Bs[c][k][tx*2];
            acc[0]=fma2(a.x,b,acc[0]);
            acc[1]=fma2(a.y,b,acc[1]);
        }
        if (kt < 31) sts(c^1);
        __syncthreads();
    }
    #pragma unroll
    for (int r = 0; r < 2; r++){
        int m = m0 + ty*2 + r;
        float h = data[(size_t)(t*BATCH + m)*DSTRIDE + DIN] * (1.0f/3.0f);
        float x0,x1; unpack2(acc[r], x0, x1);
        int n = n0 + tx*2;
        Yout[(size_t)m*LAT + n  ] = base[(size_t)m*LAT + n  ] + (x0 + b2[n  ])*h;
        Yout[(size_t)m*LAT + n+1] = base[(size_t)m*LAT + n+1] + (x1 + b2[n+1])*h;
    }
}

// ---------------- fused GRU: gi(x)+gh([Y|S]) + gates, j-tile 32, i-tile 32 ------------
__global__ __launch_bounds__(256) void k_gru(const float* __restrict__ data, int t,
                                             const float* __restrict__ bih,
                                             const float* __restrict__ bhh,
                                             const float* __restrict__ Sread,
                                             float* __restrict__ Swrite,
                                             float* __restrict__ out)
{
    __shared__ __align__(16) u64   Hs[2][32][34];
    __shared__ __align__(16) float Ws[3][2][32][36];
    const int tid = threadIdx.x;
    const int tx = tid & 15, ty = tid >> 4;
    const int i0 = blockIdx.y*32, j0 = blockIdx.x*32;
    const int sm = tid >> 3, sk = (tid & 7)*4;

    float px[4]; float4 pw0, pw1, pw2;
    u64 ar_[2], az_[2], anx[2], anh[2];
    ar_[0]=pack2(0.f,0.f); ar_[1]=ar_[0]; az_[0]=ar_[0]; az_[1]=ar_[0];
    anx[0]=ar_[0]; anx[1]=ar_[0]; anh[0]=ar_[0]; anh[1]=ar_[0];

    auto ldg = [&](int kt){
        if (kt < 8){
            int k0 = kt*32;
            const float* rp = &data[(size_t)(t*BATCH + i0 + sm)*DSTRIDE + k0 + sk];
            px[0]=rp[0]; px[1]=rp[1]; px[2]=rp[2]; px[3]=rp[3];
            const float* wp = &g_WihT[(size_t)(k0+sm)*JC + j0 + sk];
            pw0=*(const float4*)wp; pw1=*(const float4*)(wp+1024); pw2=*(const float4*)(wp+2048);
        } else {
            int kh = (kt-8)*32;
            const float* src = (kt < 24) ? g_Y : Sread;
            int kc = (kt < 24) ? kh : kh - LAT;
            float4 v = *(const float4*)&src[(size_t)(i0+sm)*LAT + kc + sk];
            px[0]=v.x; px[1]=v.y; px[2]=v.z; px[3]=v.w;
            const float* wp = &g_WhhT[(size_t)(kh+sm)*JC + j0 + sk];
            pw0=*(const float4*)wp; pw1=*(const float4*)(wp+1024); pw2=*(const float4*)(wp+2048);
        }
    };
    auto sts = [&](int b){
        Hs[b][sk+0][sm]=pack2(px[0],px[0]); Hs[b][sk+1][sm]=pack2(px[1],px[1]);
        Hs[b][sk+2][sm]=pack2(px[2],px[2]); Hs[b][sk+3][sm]=pack2(px[3],px[3]);
        *(float4*)&Ws[0][b][sm][sk]=pw0;
        *(float4*)&Ws[1][b][sm][sk]=pw1;
        *(float4*)&Ws[2][b][sm][sk]=pw2;
    };

    ldg(0); sts(0); __syncthreads();
    for (int kt = 0; kt < 40; kt++){
        int c = kt & 1;
        if (kt < 39) ldg(kt+1);
        u64* an = (kt < 8) ? anx : anh;
        #pragma unroll
        for (int k = 0; k < 32; k++){
            ulonglong2 a = *(const ulonglong2*)&Hs[c][k][ty*2];
            u64 br = *(const u64*)&Ws[0][c][k][tx*2];
            u64 bz = *(const u64*)&Ws[1][c][k][tx*2];
            u64 bn = *(const u64*)&Ws[2][c][k][tx*2];
            ar_[0]=fma2(a.x,br,ar_[0]); ar_[1]=fma2(a.y,br,ar_[1]);
            az_[0]=fma2(a.x,bz,az_[0]); az_[1]=fma2(a.y,bz,az_[1]);
            an[0] =fma2(a.x,bn,an[0]);  an[1] =fma2(a.y,bn,an[1]);
        }
        if (kt < 39) sts(c^1);
        __syncthreads();
    }

    const bool last = (t == L_SEQ-1);
    #pragma unroll
    for (int r = 0; r < 2; r++){
        int i = i0 + ty*2 + r;
        float rr[2], zz[2], nx[2], nh[2];
        unpack2(ar_[r], rr[0], rr[1]);
        unpack2(az_[r], zz[0], zz[1]);
        unpack2(anx[r], nx[0], nx[1]);
        unpack2(anh[r], nh[0], nh[1]);
        #pragma unroll
        for (int q = 0; q < 2; q++){
            int jj = j0 + tx*2 + q;
            float rg = fsigmoid(rr[q] + bih[jj] + bhh[jj]);
            float zg = fsigmoid(zz[q] + bih[HID+jj] + bhh[HID+jj]);
            float ng = ftanh((nx[q] + bih[2*HID+jj]) + rg*(nh[q] + bhh[2*HID+jj]));
            float hj = (jj < LAT) ? g_Y[(size_t)i*LAT + jj]
                                  : Sread[(size_t)i*LAT + jj - LAT];
            float v = (1.0f - zg)*ng + zg*hj;
            if (jj < LAT){
                out[(size_t)(t*BATCH + i)*LAT + jj] = v;
                Swrite[(size_t)i*LAT + jj] = v;
            }
            if (last) out[OUT2_OFF + (size_t)i*HID + jj] = v;
        }
    }
}

extern "C" void kernel_launch(void* const* d_in, const int* in_sizes, int n_in,
                              void* d_out, int out_size)
{
    const float* data = (const float*)d_in[0];
    const float* w1   = (const float*)d_in[1];
    const float* b1   = (const float*)d_in[2];
    const float* w2   = (const float*)d_in[3];
    const float* b2   = (const float*)d_in[4];
    const float* wih  = (const float*)d_in[5];
    const float* bih  = (const float*)d_in[6];
    const float* whh  = (const float*)d_in[7];
    const float* bhh  = (const float*)d_in[8];
    float* out = (float*)d_out;

    float *S0, *S1, *Y, *WihT, *WhhT;
    cudaGetSymbolAddress((void**)&S0, g_S0);
    cudaGetSymbolAddress((void**)&S1, g_S1);
    cudaGetSymbolAddress((void**)&Y,  g_Y);
    cudaGetSymbolAddress((void**)&WihT, g_WihT);
    cudaGetSymbolAddress((void**)&WhhT, g_WhhT);

    k_zero<<<(BATCH*LAT + 255)/256, 256>>>();
    k_transpose<<<dim3(JC/32, DIN/32), 256>>>(wih, DIN, WihT);
    k_transpose<<<dim3(JC/32, HID/32), 256>>>(whh, HID, WhhT);

    dim3 g1(HODE/64, BATCH/32);   // (16,8)
    dim3 g2(LAT/32,  BATCH/32);   // (16,8)

    for (int t = 0; t < L_SEQ; t++) {
        float* Sr = (t & 1) ? S1 : S0;
        float* Sw = (t & 1) ? S0 : S1;

        k_mlp1<<<g1, 256>>>(Sr, w1, b1);
        k_mlp2<<<g2, 256>>>(Sr, w2, b2, data, t, Y);
        k_mlp1<<<g1, 256>>>(Y,  w1, b1);
        k_mlp2<<<g2, 256>>>(Y,  w2, b2, data, t, Y);
        k_mlp1<<<g1, 256>>>(Y,  w1, b1);
        k_mlp2<<<g2, 256>>>(Y,  w2, b2, data, t, Y);

        int J = (t == L_SEQ-1) ? HID : LAT;
        dim3 g3(J/32, BATCH/32);
        k_gru<<<g3, 256>>>(data, t, bih, bhh, Sr, Sw, out);
    }
    (void)in_sizes; (void)n_in; (void)out_size;
}

// round 4
// speedup vs baseline: 1.4848x; 1.2474x over previous
#include <cuda_runtime.h>
#include <cstdint>

#define L_SEQ  50
#define BATCH  256
#define DIN    256
#define LAT    512
#define HODE   1024
#define HID    1024
#define DSTRIDE 257
#define JC     3072
#define OUT2_OFF (L_SEQ*BATCH*LAT)

using u64 = unsigned long long;

// ---- persistent scratch ----
__device__ float g_S0[BATCH*LAT];
__device__ float g_S1[BATCH*LAT];
__device__ float g_Y [BATCH*LAT];
__device__ float g_Z [BATCH*HODE];
__device__ float g_Q [2][BATCH*LAT];          // mlp2 split-K partials
__device__ float g_Gp[2][4][BATCH*HID];       // gru partials: r,z,nx,nh
__device__ float g_WihT[DIN*JC];
__device__ float g_WhhT[HID*JC];

__device__ __forceinline__ u64 pack2(float a, float b){
    u64 r; asm("mov.b64 %0, {%1,%2};" : "=l"(r) : "f"(a), "f"(b)); return r;
}
__device__ __forceinline__ void unpack2(u64 v, float& a, float& b){
    asm("mov.b64 {%0,%1}, %2;" : "=f"(a), "=f"(b) : "l"(v));
}
__device__ __forceinline__ u64 fma2(u64 a, u64 b, u64 c){
    u64 d; asm("fma.rn.f32x2 %0, %1, %2, %3;" : "=l"(d) : "l"(a), "l"(b), "l"(c)); return d;
}
__device__ __forceinline__ ulonglong2 dup2(float x, float y){
    ulonglong2 v; v.x = pack2(x,x); v.y = pack2(y,y); return v;
}
__device__ __forceinline__ float fsigmoid(float x){ return 1.0f/(1.0f + __expf(-x)); }
__device__ __forceinline__ float ftanh(float x){ return 1.0f - 2.0f/(__expf(2.0f*x) + 1.0f); }

__global__ void k_zero(){
    int i = blockIdx.x*blockDim.x + threadIdx.x;
    if (i < BATCH*LAT) g_S0[i] = 0.0f;
}

// W[3072][K] -> WT[K][3072]
__global__ __launch_bounds__(256) void k_transpose(const float* __restrict__ W, int K,
                                                   float* __restrict__ WT)
{
    __shared__ float tile[32][33];
    const int j0 = blockIdx.x*32, k0 = blockIdx.y*32;
    const int r = threadIdx.x >> 3, c4 = (threadIdx.x & 7)*4;
    float4 v = *(const float4*)&W[(size_t)(j0+r)*K + k0 + c4];
    tile[r][c4+0]=v.x; tile[r][c4+1]=v.y; tile[r][c4+2]=v.z; tile[r][c4+3]=v.w;
    __syncthreads();
    float4 o = make_float4(tile[c4+0][r], tile[c4+1][r], tile[c4+2][r], tile[c4+3][r]);
    *(float4*)&WT[(size_t)(k0+r)*JC + j0 + c4] = o;
}

// ======================= mlp1: g_Z = tanh(A @ W1 + b1) =======================
// A 256x512, W1 512x1024. BM=64, BN=32, BK=32, 128 thr, thread tile 4x4.
__global__ __launch_bounds__(128) void k_mlp1(const float* __restrict__ A,
                                              const float* __restrict__ W1,
                                              const float* __restrict__ b1)
{
    __shared__ __align__(16) u64   As[2][32][64];
    __shared__ __align__(16) float Bs[2][32][32];
    const int tid = threadIdx.x;
    const int tx = tid & 7, ty = tid >> 3;
    const int n0 = blockIdx.x*32, m0 = blockIdx.y*64;
    const int ap = tid & 31, aq = (tid >> 5)*8;
    const int bk = tid >> 2, bn = (tid & 3)*8;

    float4 ra0, ra1, ra2, ra3, rb0, rb1;
    u64 acc[4][2];
    #pragma unroll
    for (int r=0;r<4;r++){ acc[r][0]=0ULL; acc[r][1]=0ULL; }

    auto ldg = [&](int k0){
        const float* pa = &A[(size_t)(m0 + 2*ap)*LAT + k0 + aq];
        ra0 = *(const float4*)pa;       ra1 = *(const float4*)(pa+4);
        ra2 = *(const float4*)(pa+LAT); ra3 = *(const float4*)(pa+LAT+4);
        const float* pb = &W1[(size_t)(k0 + bk)*HODE + n0 + bn];
        rb0 = *(const float4*)pb; rb1 = *(const float4*)(pb+4);
    };
    auto sts = [&](int b){
        *(ulonglong2*)&As[b][aq+0][2*ap] = dup2(ra0.x, ra2.x);
        *(ulonglong2*)&As[b][aq+1][2*ap] = dup2(ra0.y, ra2.y);
        *(ulonglong2*)&As[b][aq+2][2*ap] = dup2(ra0.z, ra2.z);
        *(ulonglong2*)&As[b][aq+3][2*ap] = dup2(ra0.w, ra2.w);
        *(ulonglong2*)&As[b][aq+4][2*ap] = dup2(ra1.x, ra3.x);
        *(ulonglong2*)&As[b][aq+5][2*ap] = dup2(ra1.y, ra3.y);
        *(ulonglong2*)&As[b][aq+6][2*ap] = dup2(ra1.z, ra3.z);
        *(ulonglong2*)&As[b][aq+7][2*ap] = dup2(ra1.w, ra3.w);
        *(float4*)&Bs[b][bk][bn] = rb0; *(float4*)&Bs[b][bk][bn+4] = rb1;
    };

    ldg(0); sts(0); __syncthreads();
    for (int kt = 0; kt < 16; kt++){
        const int c = kt & 1;
        if (kt < 15) ldg((kt+1)*32);
        #pragma unroll
        for (int k = 0; k < 32; k++){
            ulonglong2 aA = *(const ulonglong2*)&As[c][k][ty*4];
            ulonglong2 aB = *(const ulonglong2*)&As[c][k][ty*4+2];
            ulonglong2 bb = *(const ulonglong2*)&Bs[c][k][tx*4];
            acc[0][0]=fma2(aA.x,bb.x,acc[0][0]); acc[0][1]=fma2(aA.x,bb.y,acc[0][1]);
            acc[1][0]=fma2(aA.y,bb.x,acc[1][0]); acc[1][1]=fma2(aA.y,bb.y,acc[1][1]);
            acc[2][0]=fma2(aB.x,bb.x,acc[2][0]); acc[2][1]=fma2(aB.x,bb.y,acc[2][1]);
            acc[3][0]=fma2(aB.y,bb.x,acc[3][0]); acc[3][1]=fma2(aB.y,bb.y,acc[3][1]);
        }
        if (kt < 15) sts(c^1);
        __syncthreads();
    }
    #pragma unroll
    for (int r = 0; r < 4; r++){
        const int m = m0 + ty*4 + r;
        #pragma unroll
        for (int p = 0; p < 2; p++){
            float x0,x1; unpack2(acc[r][p], x0, x1);
            const int n = n0 + tx*4 + p*2;
            g_Z[(size_t)m*HODE + n  ] = ftanh(x0 + b1[n]);
            g_Z[(size_t)m*HODE + n+1] = ftanh(x1 + b1[n+1]);
        }
    }
}

// ===== mlp2 split-K partials: g_Q[z] = g_Z[:, z*512:(z+1)*512] @ W2[z*512:,:] =====
__global__ __launch_bounds__(128) void k_mlp2(const float* __restrict__ W2)
{
    __shared__ __align__(16) u64   As[2][32][64];
    __shared__ __align__(16) float Bs[2][32][32];
    const int tid = threadIdx.x;
    const int tx = tid & 7, ty = tid >> 3;
    const int n0 = blockIdx.x*32, m0 = blockIdx.y*64;
    const int kb = blockIdx.z*512;
    const int ap = tid & 31, aq = (tid >> 5)*8;
    const int bk = tid >> 2, bn = (tid & 3)*8;

    float4 ra0, ra1, ra2, ra3, rb0, rb1;
    u64 acc[4][2];
    #pragma unroll
    for (int r=0;r<4;r++){ acc[r][0]=0ULL; acc[r][1]=0ULL; }

    auto ldg = [&](int k0){
        const float* pa = &g_Z[(size_t)(m0 + 2*ap)*HODE + kb + k0 + aq];
        ra0 = *(const float4*)pa;        ra1 = *(const float4*)(pa+4);
        ra2 = *(const float4*)(pa+HODE); ra3 = *(const float4*)(pa+HODE+4);
        const float* pb = &W2[(size_t)(kb + k0 + bk)*LAT + n0 + bn];
        rb0 = *(const float4*)pb; rb1 = *(const float4*)(pb+4);
    };
    auto sts = [&](int b){
        *(ulonglong2*)&As[b][aq+0][2*ap] = dup2(ra0.x, ra2.x);
        *(ulonglong2*)&As[b][aq+1][2*ap] = dup2(ra0.y, ra2.y);
        *(ulonglong2*)&As[b][aq+2][2*ap] = dup2(ra0.z, ra2.z);
        *(ulonglong2*)&As[b][aq+3][2*ap] = dup2(ra0.w, ra2.w);
        *(ulonglong2*)&As[b][aq+4][2*ap] = dup2(ra1.x, ra3.x);
        *(ulonglong2*)&As[b][aq+5][2*ap] = dup2(ra1.y, ra3.y);
        *(ulonglong2*)&As[b][aq+6][2*ap] = dup2(ra1.z, ra3.z);
        *(ulonglong2*)&As[b][aq+7][2*ap] = dup2(ra1.w, ra3.w);
        *(float4*)&Bs[b][bk][bn] = rb0; *(float4*)&Bs[b][bk][bn+4] = rb1;
    };

    ldg(0); sts(0); __syncthreads();
    for (int kt = 0; kt < 16; kt++){
        const int c = kt & 1;
        if (kt < 15) ldg((kt+1)*32);
        #pragma unroll
        for (int k = 0; k < 32; k++){
            ulonglong2 aA = *(const ulonglong2*)&As[c][k][ty*4];
            ulonglong2 aB = *(const ulonglong2*)&As[c][k][ty*4+2];
            ulonglong2 bb = *(const ulonglong2*)&Bs[c][k][tx*4];
            acc[0][0]=fma2(aA.x,bb.x,acc[0][0]); acc[0][1]=fma2(aA.x,bb.y,acc[0][1]);
            acc[1][0]=fma2(aA.y,bb.x,acc[1][0]); acc[1][1]=fma2(aA.y,bb.y,acc[1][1]);
            acc[2][0]=fma2(aB.x,bb.x,acc[2][0]); acc[2][1]=fma2(aB.x,bb.y,acc[2][1]);
            acc[3][0]=fma2(aB.y,bb.x,acc[3][0]); acc[3][1]=fma2(aB.y,bb.y,acc[3][1]);
        }
        if (kt < 15) sts(c^1);
        __syncthreads();
    }
    float* Q = g_Q[blockIdx.z];
    #pragma unroll
    for (int r = 0; r < 4; r++){
        const int m = m0 + ty*4 + r;
        #pragma unroll
        for (int p = 0; p < 2; p++){
            const int n = n0 + tx*4 + p*2;
            *(u64*)&Q[(size_t)m*LAT + n] = acc[r][p];
        }
    }
}

// ===== Euler combine: Y = base + (Q0 + Q1 + b2) * (dt/3) =====
__global__ __launch_bounds__(256) void k_euler(const float* __restrict__ base,
                                               const float* __restrict__ b2,
                                               const float* __restrict__ data, int t)
{
    const int i4 = blockIdx.x*256 + threadIdx.x;       // float4 index
    const int e = i4*4;
    const int m = e / LAT, n = e % LAT;
    const float h = data[(size_t)(t*BATCH + m)*DSTRIDE + DIN] * (1.0f/3.0f);
    float4 b  = *(const float4*)&base[e];
    float4 q0 = *(const float4*)&g_Q[0][e];
    float4 q1 = *(const float4*)&g_Q[1][e];
    float4 c  = *(const float4*)&b2[n];
    float4 o;
    o.x = b.x + (q0.x + q1.x + c.x)*h;
    o.y = b.y + (q0.y + q1.y + c.y)*h;
    o.z = b.z + (q0.z + q1.z + c.z)*h;
    o.w = b.w + (q0.w + q1.w + c.w)*h;
    *(float4*)&g_Y[e] = o;
}

// ===== GRU GEMM: partials for r, z, nx, nh over virtual K = [x(256) | y(512) | s(512)] =====
// split z=0: kt 0..7 -> x, kt 8..19 -> y[0:384); z=1: kt 0..3 -> y[384:512), kt 4..19 -> s
__global__ __launch_bounds__(128) void k_gru(const float* __restrict__ data, int t,
                                             const float* __restrict__ Sread)
{
    __shared__ __align__(16) u64   As[2][32][64];
    __shared__ __align__(16) float Ws[2][3][32][32];
    const int tid = threadIdx.x;
    const int tx = tid & 7, ty = tid >> 3;
    const int j0 = blockIdx.x*32, i0 = blockIdx.y*64;
    const int z  = blockIdx.z;
    const int ap = tid & 31, aq = (tid >> 5)*8;
    const int bk = tid >> 2, bn = (tid & 3)*8;

    float ax[16];
    float4 w0a,w0b,w1a,w1b,w2a,w2b;
    u64 accr[4][2], accz[4][2], accx[4][2], acch[4][2];
    #pragma unroll
    for (int r=0;r<4;r++)
        #pragma unroll
        for (int p=0;p<2;p++){ accr[r][p]=0ULL; accz[r][p]=0ULL; accx[r][p]=0ULL; acch[r][p]=0ULL; }

    auto ldg = [&](int kt){
        // A rows (batch)
        if (z == 0 && kt < 8){
            const float* p0 = &data[(size_t)(t*BATCH + i0 + 2*ap)*DSTRIDE + kt*32 + aq];
            const float* p1 = p0 + DSTRIDE;
            #pragma unroll
            for (int q = 0; q < 8; q++){ ax[q] = p0[q]; ax[8+q] = p1[q]; }
        } else {
            const float* src; int kc;
            if (z == 0)          { src = g_Y;   kc = (kt-8)*32; }
            else if (kt < 4)     { src = g_Y;   kc = 384 + kt*32; }
            else                 { src = Sread; kc = (kt-4)*32; }
            const float* p = &src[(size_t)(i0 + 2*ap)*LAT + kc + aq];
            float4 v0 = *(const float4*)p,       v1 = *(const float4*)(p+4);
            float4 v2 = *(const float4*)(p+LAT), v3 = *(const float4*)(p+LAT+4);
            ax[0]=v0.x;ax[1]=v0.y;ax[2]=v0.z;ax[3]=v0.w; ax[4]=v1.x;ax[5]=v1.y;ax[6]=v1.z;ax[7]=v1.w;
            ax[8]=v2.x;ax[9]=v2.y;ax[10]=v2.z;ax[11]=v2.w; ax[12]=v3.x;ax[13]=v3.y;ax[14]=v3.z;ax[15]=v3.w;
        }
        // B rows (transposed weights)
        const float* WT; int krow;
        if (z == 0){
            if (kt < 8){ WT = g_WihT; krow = kt*32 + bk; }
            else       { WT = g_WhhT; krow = (kt-8)*32 + bk; }
        } else {
            WT = g_WhhT;
            krow = (kt < 4) ? (384 + kt*32 + bk) : (512 + (kt-4)*32 + bk);
        }
        const float* pw = &WT[(size_t)krow*JC + j0 + bn];
        w0a = *(const float4*)pw;        w0b = *(const float4*)(pw+4);
        w1a = *(const float4*)(pw+1024); w1b = *(const float4*)(pw+1028);
        w2a = *(const float4*)(pw+2048); w2b = *(const float4*)(pw+2052);
    };
    auto sts = [&](int b){
        #pragma unroll
        for (int q = 0; q < 8; q++)
            *(ulonglong2*)&As[b][aq+q][2*ap] = dup2(ax[q], ax[8+q]);
        *(float4*)&Ws[b][0][bk][bn] = w0a; *(float4*)&Ws[b][0][bk][bn+4] = w0b;
        *(float4*)&Ws[b][1][bk][bn] = w1a; *(float4*)&Ws[b][1][bk][bn+4] = w1b;
        *(float4*)&Ws[b][2][bk][bn] = w2a; *(float4*)&Ws[b][2][bk][bn+4] = w2b;
    };
    auto compute = [&](int c, u64 (&an)[4][2]){
        #pragma unroll
        for (int k = 0; k < 32; k++){
            ulonglong2 aA = *(const ulonglong2*)&As[c][k][ty*4];
            ulonglong2 aB = *(const ulonglong2*)&As[c][k][ty*4+2];
            ulonglong2 br = *(const ulonglong2*)&Ws[c][0][k][tx*4];
            ulonglong2 bz = *(const ulonglong2*)&Ws[c][1][k][tx*4];
            ulonglong2 bn_= *(const ulonglong2*)&Ws[c][2][k][tx*4];
            accr[0][0]=fma2(aA.x,br.x,accr[0][0]); accr[0][1]=fma2(aA.x,br.y,accr[0][1]);
            accr[1][0]=fma2(aA.y,br.x,accr[1][0]); accr[1][1]=fma2(aA.y,br.y,accr[1][1]);
            accr[2][0]=fma2(aB.x,br.x,accr[2][0]); accr[2][1]=fma2(aB.x,br.y,accr[2][1]);
            accr[3][0]=fma2(aB.y,br.x,accr[3][0]); accr[3][1]=fma2(aB.y,br.y,accr[3][1]);
            accz[0][0]=fma2(aA.x,bz.x,accz[0][0]); accz[0][1]=fma2(aA.x,bz.y,accz[0][1]);
            accz[1][0]=fma2(aA.y,bz.x,accz[1][0]); accz[1][1]=fma2(aA.y,bz.y,accz[1][1]);
            accz[2][0]=fma2(aB.x,bz.x,accz[2][0]); accz[2][1]=fma2(aB.x,bz.y,accz[2][1]);
            accz[3][0]=fma2(aB.y,bz.x,accz[3][0]); accz[3][1]=fma2(aB.y,bz.y,accz[3][1]);
            an[0][0]=fma2(aA.x,bn_.x,an[0][0]); an[0][1]=fma2(aA.x,bn_.y,an[0][1]);
            an[1][0]=fma2(aA.y,bn_.x,an[1][0]); an[1][1]=fma2(aA.y,bn_.y,an[1][1]);
            an[2][0]=fma2(aB.x,bn_.x,an[2][0]); an[2][1]=fma2(aB.x,bn_.y,an[2][1]);
            an[3][0]=fma2(aB.y,bn_.x,an[3][0]); an[3][1]=fma2(aB.y,bn_.y,an[3][1]);
        }
    };

    ldg(0); sts(0); __syncthreads();
    for (int kt = 0; kt < 20; kt++){
        const int c = kt & 1;
        if (kt < 19) ldg(kt+1);
        if (z == 0 && kt < 8) compute(c, accx);
        else                  compute(c, acch);
        if (kt < 19) sts(c^1);
        __syncthreads();
    }

    #pragma unroll
    for (int r = 0; r < 4; r++){
        const int i = i0 + ty*4 + r;
        #pragma unroll
        for (int p = 0; p < 2; p++){
            const int n = j0 + tx*4 + p*2;
            const size_t off = (size_t)i*HID + n;
            *(u64*)&g_Gp[z][0][off] = accr[r][p];
            *(u64*)&g_Gp[z][1][off] = accz[r][p];
            *(u64*)&g_Gp[z][2][off] = accx[r][p];
            *(u64*)&g_Gp[z][3][off] = acch[r][p];
        }
    }
}

// ===== GRU gate combine =====
__global__ __launch_bounds__(256) void k_gates(const float* __restrict__ bih,
                                               const float* __restrict__ bhh,
                                               const float* __restrict__ Sread,
                                               float* __restrict__ Swrite,
                                               float* __restrict__ out,
                                               int t, int J)
{
    const int idx = blockIdx.x*256 + threadIdx.x;      // float2 element
    const int e = idx*2;
    if (e >= BATCH*J) return;
    const int i = e / J, j = e % J;
    const size_t off = (size_t)i*HID + j;
    float2 r0 = *(const float2*)&g_Gp[0][0][off], r1 = *(const float2*)&g_Gp[1][0][off];
    float2 z0 = *(const float2*)&g_Gp[0][1][off], z1 = *(const float2*)&g_Gp[1][1][off];
    float2 x0 = *(const float2*)&g_Gp[0][2][off], x1 = *(const float2*)&g_Gp[1][2][off];
    float2 h0 = *(const float2*)&g_Gp[0][3][off], h1 = *(const float2*)&g_Gp[1][3][off];
    const bool last = (t == L_SEQ-1);
    #pragma unroll
    for (int q = 0; q < 2; q++){
        const int jj = j + q;
        float rs = (q ? r0.y+r1.y : r0.x+r1.x) + bih[jj] + bhh[jj];
        float zs = (q ? z0.y+z1.y : z0.x+z1.x) + bih[HID+jj] + bhh[HID+jj];
        float xs = (q ? x0.y+x1.y : x0.x+x1.x) + bih[2*HID+jj];
        float hs = (q ? h0.y+h1.y : h0.x+h1.x) + bhh[2*HID+jj];
        float rg = fsigmoid(rs);
        float zg = fsigmoid(zs);
        float ng = ftanh(xs + rg*hs);
        float hv = (jj < LAT) ? g_Y[(size_t)i*LAT + jj] : Sread[(size_t)i*LAT + jj - LAT];
        float v = (1.0f - zg)*ng + zg*hv;
        if (jj < LAT){
            out[(size_t)(t*BATCH + i)*LAT + jj] = v;
            Swrite[(size_t)i*LAT + jj] = v;
        }
        if (last) out[OUT2_OFF + (size_t)i*HID + jj] = v;
    }
}

extern "C" void kernel_launch(void* const* d_in, const int* in_sizes, int n_in,
                              void* d_out, int out_size)
{
    const float* data = (const float*)d_in[0];
    const float* w1   = (const float*)d_in[1];
    const float* b1   = (const float*)d_in[2];
    const float* w2   = (const float*)d_in[3];
    const float* b2   = (const float*)d_in[4];
    const float* wih  = (const float*)d_in[5];
    const float* bih  = (const float*)d_in[6];
    const float* whh  = (const float*)d_in[7];
    const float* bhh  = (const float*)d_in[8];
    float* out = (float*)d_out;

    float *S0, *S1, *Y, *WihT, *WhhT;
    cudaGetSymbolAddress((void**)&S0, g_S0);
    cudaGetSymbolAddress((void**)&S1, g_S1);
    cudaGetSymbolAddress((void**)&Y,  g_Y);
    cudaGetSymbolAddress((void**)&WihT, g_WihT);
    cudaGetSymbolAddress((void**)&WhhT, g_WhhT);

    k_zero<<<(BATCH*LAT + 255)/256, 256>>>();
    k_transpose<<<dim3(JC/32, DIN/32), 256>>>(wih, DIN, WihT);
    k_transpose<<<dim3(JC/32, HID/32), 256>>>(whh, HID, WhhT);

    const dim3 g1(HODE/32, BATCH/64);        // (32,4) = 128
    const dim3 g2(LAT/32,  BATCH/64, 2);     // (16,4,2) = 128
    const dim3 ge(BATCH*LAT/4/256);          // 128

    for (int t = 0; t < L_SEQ; t++) {
        float* Sr = (t & 1) ? S1 : S0;
        float* Sw = (t & 1) ? S0 : S1;

        const float* base = Sr;
        for (int s = 0; s < 3; s++){
            k_mlp1<<<g1, 128>>>(base, w1, b1);
            k_mlp2<<<g2, 128>>>(w2);
            k_euler<<<ge, 256>>>(base, b2, data, t);
            base = Y;
        }

        const int J = (t == L_SEQ-1) ? HID : LAT;
        dim3 g3(J/32, BATCH/64, 2);
        k_gru<<<g3, 128>>>(data, t, Sr);
        k_gates<<<(BATCH*J/2 + 255)/256, 256>>>(bih, bhh, Sr, Sw, out, t, J);
    }
    (void)in_sizes; (void)n_in; (void)out_size;
}

// round 7
// speedup vs baseline: 1.5967x; 1.0754x over previous
#include <cuda_runtime.h>
#include <cstdint>

#define L_SEQ  50
#define BATCH  256
#define DIN    256
#define LAT    512
#define HODE   1024
#define HID    1024
#define DSTRIDE 257
#define JC     3072
#define OUT2_OFF (L_SEQ*BATCH*LAT)

using u64 = unsigned long long;

// ---- persistent scratch ----
__device__ float g_S0[BATCH*LAT];
__device__ float g_S1[BATCH*LAT];
__device__ float g_Y [BATCH*LAT];
__device__ float g_P [2][BATCH*HODE];        // mlp1 raw split-K partials
__device__ float g_Q [4][BATCH*LAT];         // mlp2 split-K partials
__device__ float g_Gp[4][4][BATCH*HID];      // gru partials: r,z,nx,nh per K-slice
__device__ float g_WihT[DIN*JC];
__device__ float g_WhhT[HID*JC];

__device__ __forceinline__ u64 pack2(float a, float b){
    u64 r; asm("mov.b64 %0, {%1,%2};" : "=l"(r) : "f"(a), "f"(b)); return r;
}
__device__ __forceinline__ void unpack2(u64 v, float& a, float& b){
    asm("mov.b64 {%0,%1}, %2;" : "=f"(a), "=f"(b) : "l"(v));
}
__device__ __forceinline__ u64 fma2(u64 a, u64 b, u64 c){
    u64 d; asm("fma.rn.f32x2 %0, %1, %2, %3;" : "=l"(d) : "l"(a), "l"(b), "l"(c)); return d;
}
__device__ __forceinline__ ulonglong2 dup2(float x, float y){
    ulonglong2 v; v.x = pack2(x,x); v.y = pack2(y,y); return v;
}
__device__ __forceinline__ float fsigmoid(float x){ return 1.0f/(1.0f + __expf(-x)); }
__device__ __forceinline__ float ftanh(float x){ return 1.0f - 2.0f/(__expf(2.0f*x) + 1.0f); }

__global__ void k_zero(){
    int i = blockIdx.x*blockDim.x + threadIdx.x;
    if (i < BATCH*LAT) g_S0[i] = 0.0f;
}

// W[3072][K] -> WT[K][3072]
__global__ __launch_bounds__(256) void k_transpose(const float* __restrict__ W, int K,
                                                   float* __restrict__ WT)
{
    __shared__ float tile[32][33];
    const int j0 = blockIdx.x*32, k0 = blockIdx.y*32;
    const int r = threadIdx.x >> 3, c4 = (threadIdx.x & 7)*4;
    float4 v = *(const float4*)&W[(size_t)(j0+r)*K + k0 + c4];
    tile[r][c4+0]=v.x; tile[r][c4+1]=v.y; tile[r][c4+2]=v.z; tile[r][c4+3]=v.w;
    __syncthreads();
    float4 o = make_float4(tile[c4+0][r], tile[c4+1][r], tile[c4+2][r], tile[c4+3][r]);
    *(float4*)&WT[(size_t)(k0+r)*JC + j0 + c4] = o;
}

// ============ mlp1 partial: g_P[z] = A[:, z*256:(z+1)*256] @ W1[z*256:,:] ============
// BM=64, BN=64, BK=32, 256 thr, 4x4 thread tiles. grid (16,4,2)=128 blocks.
__global__ __launch_bounds__(256) void k_mlp1(const float* __restrict__ A,
                                              const float* __restrict__ W1)
{
    __shared__ __align__(16) u64   As[2][32][66];
    __shared__ __align__(16) float Bs[2][32][72];
    const int tid = threadIdx.x;
    const int tx = tid & 15, ty = tid >> 4;
    const int n0 = blockIdx.x*64, m0 = blockIdx.y*64, kb = blockIdx.z*256;
    const int ap = tid & 31, aq = (tid >> 5)*4;
    const int br = tid >> 3, bc = (tid & 7)*8;

    float4 ra, rb, wb0, wb1;
    u64 acc[4][2];
    #pragma unroll
    for (int r=0;r<4;r++){ acc[r][0]=0ULL; acc[r][1]=0ULL; }

    auto ldg = [&](int k0){
        const float* pa = &A[(size_t)(m0 + 2*ap)*LAT + kb + k0 + aq];
        ra = *(const float4*)pa; rb = *(const float4*)(pa + LAT);
        const float* pb = &W1[(size_t)(kb + k0 + br)*HODE + n0 + bc];
        wb0 = *(const float4*)pb; wb1 = *(const float4*)(pb+4);
    };
    auto sts = [&](int b){
        *(ulonglong2*)&As[b][aq+0][2*ap] = dup2(ra.x, rb.x);
        *(ulonglong2*)&As[b][aq+1][2*ap] = dup2(ra.y, rb.y);
        *(ulonglong2*)&As[b][aq+2][2*ap] = dup2(ra.z, rb.z);
        *(ulonglong2*)&As[b][aq+3][2*ap] = dup2(ra.w, rb.w);
        *(float4*)&Bs[b][br][bc] = wb0; *(float4*)&Bs[b][br][bc+4] = wb1;
    };

    ldg(0); sts(0); __syncthreads();
    for (int kt = 0; kt < 8; kt++){
        const int c = kt & 1;
        if (kt < 7) ldg((kt+1)*32);
        #pragma unroll
        for (int k = 0; k < 32; k++){
            ulonglong2 aA = *(const ulonglong2*)&As[c][k][ty*4];
            ulonglong2 aB = *(const ulonglong2*)&As[c][k][ty*4+2];
            ulonglong2 bb = *(const ulonglong2*)&Bs[c][k][tx*4];
            acc[0][0]=fma2(aA.x,bb.x,acc[0][0]); acc[0][1]=fma2(aA.x,bb.y,acc[0][1]);
            acc[1][0]=fma2(aA.y,bb.x,acc[1][0]); acc[1][1]=fma2(aA.y,bb.y,acc[1][1]);
            acc[2][0]=fma2(aB.x,bb.x,acc[2][0]); acc[2][1]=fma2(aB.x,bb.y,acc[2][1]);
            acc[3][0]=fma2(aB.y,bb.x,acc[3][0]); acc[3][1]=fma2(aB.y,bb.y,acc[3][1]);
        }
        if (kt < 7) sts(c^1);
        __syncthreads();
    }
    float* P = g_P[blockIdx.z];
    #pragma unroll
    for (int r = 0; r < 4; r++){
        const int m = m0 + ty*4 + r;
        #pragma unroll
        for (int p = 0; p < 2; p++)
            *(u64*)&P[(size_t)m*HODE + n0 + tx*4 + p*2] = acc[r][p];
    }
}

// ===== mlp2 partial: A = tanh(P0+P1+b1) fused in staging; g_Q[z] over K-slice =====
// grid (8,4,4)=128 blocks.
__global__ __launch_bounds__(256) void k_mlp2(const float* __restrict__ W2,
                                              const float* __restrict__ b1)
{
    __shared__ __align__(16) u64   As[2][32][66];
    __shared__ __align__(16) float Bs[2][32][72];
    const int tid = threadIdx.x;
    const int tx = tid & 15, ty = tid >> 4;
    const int n0 = blockIdx.x*64, m0 = blockIdx.y*64, kb = blockIdx.z*256;
    const int ap = tid & 31, aq = (tid >> 5)*4;
    const int br = tid >> 3, bc = (tid & 7)*8;

    float4 ra, rb, wb0, wb1;
    u64 acc[4][2];
    #pragma unroll
    for (int r=0;r<4;r++){ acc[r][0]=0ULL; acc[r][1]=0ULL; }

    auto ldg = [&](int k0){
        const size_t off = (size_t)(m0 + 2*ap)*HODE + kb + k0 + aq;
        float4 a0 = *(const float4*)&g_P[0][off];
        float4 a1 = *(const float4*)&g_P[1][off];
        float4 c0 = *(const float4*)&b1[kb + k0 + aq];
        float4 d0 = *(const float4*)&g_P[0][off + HODE];
        float4 d1 = *(const float4*)&g_P[1][off + HODE];
        ra.x = ftanh(a0.x + a1.x + c0.x); ra.y = ftanh(a0.y + a1.y + c0.y);
        ra.z = ftanh(a0.z + a1.z + c0.z); ra.w = ftanh(a0.w + a1.w + c0.w);
        rb.x = ftanh(d0.x + d1.x + c0.x); rb.y = ftanh(d0.y + d1.y + c0.y);
        rb.z = ftanh(d0.z + d1.z + c0.z); rb.w = ftanh(d0.w + d1.w + c0.w);
        const float* pb = &W2[(size_t)(kb + k0 + br)*LAT + n0 + bc];
        wb0 = *(const float4*)pb; wb1 = *(const float4*)(pb+4);
    };
    auto sts = [&](int b){
        *(ulonglong2*)&As[b][aq+0][2*ap] = dup2(ra.x, rb.x);
        *(ulonglong2*)&As[b][aq+1][2*ap] = dup2(ra.y, rb.y);
        *(ulonglong2*)&As[b][aq+2][2*ap] = dup2(ra.z, rb.z);
        *(ulonglong2*)&As[b][aq+3][2*ap] = dup2(ra.w, rb.w);
        *(float4*)&Bs[b][br][bc] = wb0; *(float4*)&Bs[b][br][bc+4] = wb1;
    };

    ldg(0); sts(0); __syncthreads();
    for (int kt = 0; kt < 8; kt++){
        const int c = kt & 1;
        if (kt < 7) ldg((kt+1)*32);
        #pragma unroll
        for (int k = 0; k < 32; k++){
            ulonglong2 aA = *(const ulonglong2*)&As[c][k][ty*4];
            ulonglong2 aB = *(const ulonglong2*)&As[c][k][ty*4+2];
            ulonglong2 bb = *(const ulonglong2*)&Bs[c][k][tx*4];
            acc[0][0]=fma2(aA.x,bb.x,acc[0][0]); acc[0][1]=fma2(aA.x,bb.y,acc[0][1]);
            acc[1][0]=fma2(aA.y,bb.x,acc[1][0]); acc[1][1]=fma2(aA.y,bb.y,acc[1][1]);
            acc[2][0]=fma2(aB.x,bb.x,acc[2][0]); acc[2][1]=fma2(aB.x,bb.y,acc[2][1]);
            acc[3][0]=fma2(aB.y,bb.x,acc[3][0]); acc[3][1]=fma2(aB.y,bb.y,acc[3][1]);
        }
        if (kt < 7) sts(c^1);
        __syncthreads();
    }
    float* Q = g_Q[blockIdx.z];
    #pragma unroll
    for (int r = 0; r < 4; r++){
        const int m = m0 + ty*4 + r;
        #pragma unroll
        for (int p = 0; p < 2; p++)
            *(u64*)&Q[(size_t)m*LAT + n0 + tx*4 + p*2] = acc[r][p];
    }
}

// ===== Euler combine: Y = base + (Q0+Q1+Q2+Q3 + b2) * (dt/3) =====
__global__ __launch_bounds__(256) void k_euler(const float* __restrict__ base,
                                               const float* __restrict__ b2,
                                               const float* __restrict__ data, int t)
{
    const int e = (blockIdx.x*256 + threadIdx.x)*4;
    const int m = e / LAT, n = e % LAT;
    const float h = data[(size_t)(t*BATCH + m)*DSTRIDE + DIN] * (1.0f/3.0f);
    float4 b  = *(const float4*)&base[e];
    float4 q0 = *(const float4*)&g_Q[0][e];
    float4 q1 = *(const float4*)&g_Q[1][e];
    float4 q2 = *(const float4*)&g_Q[2][e];
    float4 q3 = *(const float4*)&g_Q[3][e];
    float4 c  = *(const float4*)&b2[n];
    float4 o;
    o.x = b.x + (q0.x + q1.x + q2.x + q3.x + c.x)*h;
    o.y = b.y + (q0.y + q1.y + q2.y + q3.y + c.y)*h;
    o.z = b.z + (q0.z + q1.z + q2.z + q3.z + c.z)*h;
    o.w = b.w + (q0.w + q1.w + q2.w + q3.w + c.w)*h;
    *(float4*)&g_Y[e] = o;
}

// ===== GRU partials over virtual K = [x(256) | y(512) | s(512)], 4 slices of 320 =====
// BM=64 (batch), BN=64 (gate cols), 256 thr. grid (J/64, 4, 4).
__global__ __launch_bounds__(256) void k_gru(const float* __restrict__ data, int t,
                                             const float* __restrict__ Sread)
{
    __shared__ __align__(16) u64   As[2][32][66];
    __shared__ __align__(16) float Ws[2][3][32][72];
    const int tid = threadIdx.x;
    const int tx = tid & 15, ty = tid >> 4;
    const int j0 = blockIdx.x*64, i0 = blockIdx.y*64;
    const int z  = blockIdx.z;
    const int ap = tid & 31, aq = (tid >> 5)*4;
    const int br = tid >> 3, bc = (tid & 7)*8;

    float ra[4], rb[4];
    float4 w0a,w0b,w1a,w1b,w2a,w2b;
    u64 accr[4][2], accz[4][2], accx[4][2], acch[4][2];
    #pragma unroll
    for (int r=0;r<4;r++)
        #pragma unroll
        for (int p=0;p<2;p++){ accr[r][p]=0ULL; accz[r][p]=0ULL; accx[r][p]=0ULL; acch[r][p]=0ULL; }

    auto ldg = [&](int kt){
        const int kv = z*320 + kt*32;
        if (kv < 256){
            const float* p0 = &data[(size_t)(t*BATCH + i0 + 2*ap)*DSTRIDE + kv + aq];
            const float* p1 = p0 + DSTRIDE;
            #pragma unroll
            for (int q = 0; q < 4; q++){ ra[q] = p0[q]; rb[q] = p1[q]; }
        } else {
            const float* src = (kv < 768) ? g_Y : Sread;
            const int kc = (kv < 768) ? kv - 256 : kv - 768;
            const float* p = &src[(size_t)(i0 + 2*ap)*LAT + kc + aq];
            float4 v0 = *(const float4*)p, v1 = *(const float4*)(p + LAT);
            ra[0]=v0.x; ra[1]=v0.y; ra[2]=v0.z; ra[3]=v0.w;
            rb[0]=v1.x; rb[1]=v1.y; rb[2]=v1.z; rb[3]=v1.w;
        }
        const float* WT = (kv < 256) ? g_WihT : g_WhhT;
        const int kvw = (kv < 256) ? kv : kv - 256;
        const float* pw = &WT[(size_t)(kvw + br)*JC + j0 + bc];
        w0a = *(const float4*)pw;        w0b = *(const float4*)(pw+4);
        w1a = *(const float4*)(pw+1024); w1b = *(const float4*)(pw+1028);
        w2a = *(const float4*)(pw+2048); w2b = *(const float4*)(pw+2052);
    };
    auto sts = [&](int b){
        *(ulonglong2*)&As[b][aq+0][2*ap] = dup2(ra[0], rb[0]);
        *(ulonglong2*)&As[b][aq+1][2*ap] = dup2(ra[1], rb[1]);
        *(ulonglong2*)&As[b][aq+2][2*ap] = dup2(ra[2], rb[2]);
        *(ulonglong2*)&As[b][aq+3][2*ap] = dup2(ra[3], rb[3]);
        *(float4*)&Ws[b][0][br][bc] = w0a; *(float4*)&Ws[b][0][br][bc+4] = w0b;
        *(float4*)&Ws[b][1][br][bc] = w1a; *(float4*)&Ws[b][1][br][bc+4] = w1b;
        *(float4*)&Ws[b][2][br][bc] = w2a; *(float4*)&Ws[b][2][br][bc+4] = w2b;
    };

    ldg(0); sts(0); __syncthreads();
    for (int kt = 0; kt < 10; kt++){
        const int c = kt & 1;
        const bool isx = (z*320 + kt*32) < 256;
        if (kt < 9) ldg(kt+1);
        u64 (&an)[4][2] = isx ? accx : acch;
        #pragma unroll
        for (int k = 0; k < 32; k++){
            ulonglong2 aA = *(const ulonglong2*)&As[c][k][ty*4];
            ulonglong2 aB = *(const ulonglong2*)&As[c][k][ty*4+2];
            ulonglong2 br_= *(const ulonglong2*)&Ws[c][0][k][tx*4];
            ulonglong2 bz = *(const ulonglong2*)&Ws[c][1][k][tx*4];
            ulonglong2 bn_= *(const ulonglong2*)&Ws[c][2][k][tx*4];
            accr[0][0]=fma2(aA.x,br_.x,accr[0][0]); accr[0][1]=fma2(aA.x,br_.y,accr[0][1]);
            accr[1][0]=fma2(aA.y,br_.x,accr[1][0]); accr[1][1]=fma2(aA.y,br_.y,accr[1][1]);
            accr[2][0]=fma2(aB.x,br_.x,accr[2][0]); accr[2][1]=fma2(aB.x,br_.y,accr[2][1]);
            accr[3][0]=fma2(aB.y,br_.x,accr[3][0]); accr[3][1]=fma2(aB.y,br_.y,accr[3][1]);
            accz[0][0]=fma2(aA.x,bz.x,accz[0][0]); accz[0][1]=fma2(aA.x,bz.y,accz[0][1]);
            accz[1][0]=fma2(aA.y,bz.x,accz[1][0]); accz[1][1]=fma2(aA.y,bz.y,accz[1][1]);
            accz[2][0]=fma2(aB.x,bz.x,accz[2][0]); accz[2][1]=fma2(aB.x,bz.y,accz[2][1]);
            accz[3][0]=fma2(aB.y,bz.x,accz[3][0]); accz[3][1]=fma2(aB.y,bz.y,accz[3][1]);
            an[0][0]=fma2(aA.x,bn_.x,an[0][0]); an[0][1]=fma2(aA.x,bn_.y,an[0][1]);
            an[1][0]=fma2(aA.y,bn_.x,an[1][0]); an[1][1]=fma2(aA.y,bn_.y,an[1][1]);
            an[2][0]=fma2(aB.x,bn_.x,an[2][0]); an[2][1]=fma2(aB.x,bn_.y,an[2][1]);
            an[3][0]=fma2(aB.y,bn_.x,an[3][0]); an[3][1]=fma2(aB.y,bn_.y,an[3][1]);
        }
        if (kt < 9) sts(c^1);
        __syncthreads();
    }

    #pragma unroll
    for (int r = 0; r < 4; r++){
        const int i = i0 + ty*4 + r;
        #pragma unroll
        for (int p = 0; p < 2; p++){
            const size_t off = (size_t)i*HID + j0 + tx*4 + p*2;
            *(u64*)&g_Gp[z][0][off] = accr[r][p];
            *(u64*)&g_Gp[z][1][off] = accz[r][p];
            *(u64*)&g_Gp[z][2][off] = accx[r][p];
            *(u64*)&g_Gp[z][3][off] = acch[r][p];
        }
    }
}

// ===== GRU gate combine (4 partial slices) =====
__global__ __launch_bounds__(256) void k_gates(const float* __restrict__ bih,
                                               const float* __restrict__ bhh,
                                               const float* __restrict__ Sread,
                                               float* __restrict__ Swrite,
                                               float* __restrict__ out,
                                               int t, int J)
{
    const int e = (blockIdx.x*256 + threadIdx.x)*2;
    if (e >= BATCH*J) return;
    const int i = e / J, j = e % J;
    const size_t off = (size_t)i*HID + j;
    float rs0 = 0.f, rs1 = 0.f, zs0 = 0.f, zs1 = 0.f;
    float xs0 = 0.f, xs1 = 0.f, hs0 = 0.f, hs1 = 0.f;
    #pragma unroll
    for (int zz = 0; zz < 4; zz++){
        float2 rv = *(const float2*)&g_Gp[zz][0][off];
        float2 zv = *(const float2*)&g_Gp[zz][1][off];
        float2 xv = *(const float2*)&g_Gp[zz][2][off];
        float2 hv = *(const float2*)&g_Gp[zz][3][off];
        rs0 += rv.x; rs1 += rv.y;  zs0 += zv.x; zs1 += zv.y;
        xs0 += xv.x; xs1 += xv.y;  hs0 += hv.x; hs1 += hv.y;
    }
    const bool last = (t == L_SEQ-1);
    #pragma unroll
    for (int q = 0; q < 2; q++){
        const int jj = j + q;
        float rg = fsigmoid((q ? rs1 : rs0) + bih[jj] + bhh[jj]);
        float zg = fsigmoid((q ? zs1 : zs0) + bih[HID+jj] + bhh[HID+jj]);
        float ng = ftanh(((q ? xs1 : xs0) + bih[2*HID+jj]) + rg*((q ? hs1 : hs0) + bhh[2*HID+jj]));
        float hv = (jj < LAT) ? g_Y[(size_t)i*LAT + jj] : Sread[(size_t)i*LAT + jj - LAT];
        float v = (1.0f - zg)*ng + zg*hv;
        if (jj < LAT){
            out[(size_t)(t*BATCH + i)*LAT + jj] = v;
            Swrite[(size_t)i*LAT + jj] = v;
        }
        if (last) out[OUT2_OFF + (size_t)i*HID + jj] = v;
    }
}

extern "C" void kernel_launch(void* const* d_in, const int* in_sizes, int n_in,
                              void* d_out, int out_size)
{
    const float* data = (const float*)d_in[0];
    const float* w1   = (const float*)d_in[1];
    const float* b1   = (const float*)d_in[2];
    const float* w2   = (const float*)d_in[3];
    const float* b2   = (const float*)d_in[4];
    const float* wih  = (const float*)d_in[5];
    const float* bih  = (const float*)d_in[6];
    const float* whh  = (const float*)d_in[7];
    const float* bhh  = (const float*)d_in[8];
    float* out = (float*)d_out;

    float *S0, *S1, *Y, *WihT, *WhhT;
    cudaGetSymbolAddress((void**)&S0, g_S0);
    cudaGetSymbolAddress((void**)&S1, g_S1);
    cudaGetSymbolAddress((void**)&Y,  g_Y);
    cudaGetSymbolAddress((void**)&WihT, g_WihT);
    cudaGetSymbolAddress((void**)&WhhT, g_WhhT);

    k_zero<<<(BATCH*LAT + 255)/256, 256>>>();
    k_transpose<<<dim3(JC/32, DIN/32), 256>>>(wih, DIN, WihT);
    k_transpose<<<dim3(JC/32, HID/32), 256>>>(whh, HID, WhhT);

    const dim3 g1(HODE/64, BATCH/64, 2);     // (16,4,2) = 128
    const dim3 g2(LAT/64,  BATCH/64, 4);     // (8,4,4)  = 128
    const dim3 ge(BATCH*LAT/4/256);          // 128

    for (int t = 0; t < L_SEQ; t++) {
        float* Sr = (t & 1) ? S1 : S0;
        float* Sw = (t & 1) ? S0 : S1;

        const float* base = Sr;
        for (int s = 0; s < 3; s++){
            k_mlp1<<<g1, 256>>>(base, w1);
            k_mlp2<<<g2, 256>>>(w2, b1);
            k_euler<<<ge, 256>>>(base, b2, data, t);
            base = Y;
        }

        const int J = (t == L_SEQ-1) ? HID : LAT;
        dim3 g3(J/64, BATCH/64, 4);
        k_gru<<<g3, 256>>>(data, t, Sr);
        k_gates<<<(BATCH*J/2 + 255)/256, 256>>>(bih, bhh, Sr, Sw, out, t, J);
    }
    (void)in_sizes; (void)n_in; (void)out_size;
}